// round 4
// baseline (speedup 1.0000x reference)
#include <cuda_runtime.h>
#include <cstdint>

// Problem constants (fixed by the dataset)
#define NN 500000
#define GG 1000

// ---------------------------------------------------------------------------
// Scratch (device globals).
// g_deg[n]: lo16 = deg_in, hi16 = deg_out (packed u16 fields in a u32).
// Max degree under the uniform-random edge model is ~50 << 65535.
// ---------------------------------------------------------------------------
__device__ unsigned g_deg [NN];
__device__ float    g_agg1[NN];   // layer-1 scalar aggregation
__device__ float    g_t   [NN];   // s * isi * iso (layer-2 propagand)
__device__ float    g_A   [NN];   // layer-2 scalar aggregation
__device__ float    g_S   [GG];   // pooled scalar sum per graph
__device__ float    g_cnt [GG];   // nodes per graph

#define ONE_IN  1u
#define ONE_OUT (1u << 16)

__device__ __forceinline__ void red_f32(float* p, float v) {
    asm volatile("red.global.add.f32 [%0], %1;" :: "l"(p), "f"(v) : "memory");
}
__device__ __forceinline__ void red_u32(unsigned* p, unsigned v) {
    asm volatile("red.global.add.u32 [%0], %1;" :: "l"(p), "r"(v) : "memory");
}

// ---------------------------------------------------------------------------
// K1: degree counting, packed u32 (u16 in | u16 out). 8 edges / thread.
// ---------------------------------------------------------------------------
__global__ void k_deg(const int* __restrict__ src, const int* __restrict__ dst, int E) {
    int i = blockIdx.x * blockDim.x + threadIdx.x;
    int base = i << 3;
    if (base + 7 < E) {
        int4 s0 = *reinterpret_cast<const int4*>(src + base);
        int4 s1 = *reinterpret_cast<const int4*>(src + base + 4);
        int4 d0 = *reinterpret_cast<const int4*>(dst + base);
        int4 d1 = *reinterpret_cast<const int4*>(dst + base + 4);
        red_u32(&g_deg[s0.x], ONE_OUT); red_u32(&g_deg[s0.y], ONE_OUT);
        red_u32(&g_deg[s0.z], ONE_OUT); red_u32(&g_deg[s0.w], ONE_OUT);
        red_u32(&g_deg[s1.x], ONE_OUT); red_u32(&g_deg[s1.y], ONE_OUT);
        red_u32(&g_deg[s1.z], ONE_OUT); red_u32(&g_deg[s1.w], ONE_OUT);
        red_u32(&g_deg[d0.x], ONE_IN);  red_u32(&g_deg[d0.y], ONE_IN);
        red_u32(&g_deg[d0.z], ONE_IN);  red_u32(&g_deg[d0.w], ONE_IN);
        red_u32(&g_deg[d1.x], ONE_IN);  red_u32(&g_deg[d1.y], ONE_IN);
        red_u32(&g_deg[d1.z], ONE_IN);  red_u32(&g_deg[d1.w], ONE_IN);
    } else {
        for (int e = base; e < E; ++e) {
            red_u32(&g_deg[src[e]], ONE_OUT);
            red_u32(&g_deg[dst[e]], ONE_IN);
        }
    }
}

// ---------------------------------------------------------------------------
// K2: layer-1 scatter with inline x0.
//     agg1[dst] += deg_in[src] * rsqrt(max(deg_out[src],1)).  8 edges/thread.
// ---------------------------------------------------------------------------
__device__ __forceinline__ float x0_of(unsigned p) {
    float di = (float)(p & 0xffffu);
    float dq = (float)(p >> 16);
    return di * rsqrtf(fmaxf(dq, 1.0f));
}

__global__ void k_scatter1(const int* __restrict__ src, const int* __restrict__ dst, int E) {
    int i = blockIdx.x * blockDim.x + threadIdx.x;
    int base = i << 3;
    if (base + 7 < E) {
        int4 s0 = *reinterpret_cast<const int4*>(src + base);
        int4 s1 = *reinterpret_cast<const int4*>(src + base + 4);
        int4 d0 = *reinterpret_cast<const int4*>(dst + base);
        int4 d1 = *reinterpret_cast<const int4*>(dst + base + 4);
        float v0 = x0_of(__ldg(&g_deg[s0.x]));
        float v1 = x0_of(__ldg(&g_deg[s0.y]));
        float v2 = x0_of(__ldg(&g_deg[s0.z]));
        float v3 = x0_of(__ldg(&g_deg[s0.w]));
        float v4 = x0_of(__ldg(&g_deg[s1.x]));
        float v5 = x0_of(__ldg(&g_deg[s1.y]));
        float v6 = x0_of(__ldg(&g_deg[s1.z]));
        float v7 = x0_of(__ldg(&g_deg[s1.w]));
        red_f32(&g_agg1[d0.x], v0); red_f32(&g_agg1[d0.y], v1);
        red_f32(&g_agg1[d0.z], v2); red_f32(&g_agg1[d0.w], v3);
        red_f32(&g_agg1[d1.x], v4); red_f32(&g_agg1[d1.y], v5);
        red_f32(&g_agg1[d1.z], v6); red_f32(&g_agg1[d1.w], v7);
    } else {
        for (int e = base; e < E; ++e)
            red_f32(&g_agg1[dst[e]], x0_of(__ldg(&g_deg[src[e]])));
    }
}

// ---------------------------------------------------------------------------
// K3: t[n] = agg1[n] * isi[n] * iso[n]; also zeroes A and the pool buffers.
// ---------------------------------------------------------------------------
__global__ void k_t(int N) {
    int i = blockIdx.x * blockDim.x + threadIdx.x;
    if (i < GG) { g_S[i] = 0.0f; g_cnt[i] = 0.0f; }
    if (i >= N) return;
    unsigned p = g_deg[i];
    float isi = rsqrtf(fmaxf((float)(p & 0xffffu), 1.0f));
    float iso = rsqrtf(fmaxf((float)(p >> 16), 1.0f));
    g_t[i] = g_agg1[i] * isi * iso;
    g_A[i] = 0.0f;
}

// ---------------------------------------------------------------------------
// K4: layer-2 scalar scatter  A[dst] += t[src].  8 edges/thread.
// ---------------------------------------------------------------------------
__global__ void k_scatter2(const int* __restrict__ src, const int* __restrict__ dst, int E) {
    int i = blockIdx.x * blockDim.x + threadIdx.x;
    int base = i << 3;
    if (base + 7 < E) {
        int4 s0 = *reinterpret_cast<const int4*>(src + base);
        int4 s1 = *reinterpret_cast<const int4*>(src + base + 4);
        int4 d0 = *reinterpret_cast<const int4*>(dst + base);
        int4 d1 = *reinterpret_cast<const int4*>(dst + base + 4);
        float v0 = __ldg(&g_t[s0.x]);
        float v1 = __ldg(&g_t[s0.y]);
        float v2 = __ldg(&g_t[s0.z]);
        float v3 = __ldg(&g_t[s0.w]);
        float v4 = __ldg(&g_t[s1.x]);
        float v5 = __ldg(&g_t[s1.y]);
        float v6 = __ldg(&g_t[s1.z]);
        float v7 = __ldg(&g_t[s1.w]);
        red_f32(&g_A[d0.x], v0); red_f32(&g_A[d0.y], v1);
        red_f32(&g_A[d0.z], v2); red_f32(&g_A[d0.w], v3);
        red_f32(&g_A[d1.x], v4); red_f32(&g_A[d1.y], v5);
        red_f32(&g_A[d1.z], v6); red_f32(&g_A[d1.w], v7);
    } else {
        for (int e = base; e < E; ++e)
            red_f32(&g_A[dst[e]], __ldg(&g_t[src[e]]));
    }
}

// ---------------------------------------------------------------------------
// K5: scalar pooling.  u = A * isi;  S[g] += u; cnt[g] += 1.
//     graph_ids sorted -> warp-uniform fast path (2 REDs per warp).
// ---------------------------------------------------------------------------
__global__ void k_pool(const int* __restrict__ gid, int N) {
    int i = blockIdx.x * blockDim.x + threadIdx.x;
    bool valid = (i < N);
    float u = 0.0f;
    int g = -1;
    if (valid) {
        unsigned p = g_deg[i];
        u = g_A[i] * rsqrtf(fmaxf((float)(p & 0xffffu), 1.0f));
        g = gid[i];
    }
    int  g0  = __shfl_sync(0xffffffffu, g, 0);
    bool uni = __all_sync(0xffffffffu, valid && (g == g0));
    if (uni) {
#pragma unroll
        for (int o = 16; o > 0; o >>= 1)
            u += __shfl_xor_sync(0xffffffffu, u, o);
        if ((threadIdx.x & 31) == 0) {
            red_f32(&g_S[g0], u);
            red_f32(&g_cnt[g0], 32.0f);
        }
    } else if (valid) {
        red_f32(&g_S[g], u);
        red_f32(&g_cnt[g], 1.0f);
    }
}

// ---------------------------------------------------------------------------
// K6: out[g][c] = (S_g / max(cnt_g,1)) * rW_c
//     rW_c = relu(relu(W1) @ W2) @ Wlast[:,c]
// ---------------------------------------------------------------------------
__global__ void k_final(const float* __restrict__ W1, const float* __restrict__ W2,
                        const float* __restrict__ Wlast, float* __restrict__ out, int G) {
    int t = blockIdx.x * blockDim.x + threadIdx.x;
    if (t >= G * 8) return;
    int g = t >> 3;
    int c = t & 7;
    float rw = 0.0f;
#pragma unroll
    for (int k = 0; k < 8; ++k) {
        float q = 0.0f;
#pragma unroll
        for (int j = 0; j < 8; ++j)
            q += fmaxf(__ldg(&W1[j]), 0.0f) * __ldg(&W2[j * 8 + k]);
        rw += fmaxf(q, 0.0f) * __ldg(&Wlast[k * 8 + c]);
    }
    out[t] = (g_S[g] / fmaxf(g_cnt[g], 1.0f)) * rw;
}

// ---------------------------------------------------------------------------
// kernel_launch — graph-capturable, allocation-free.
// Inputs (metadata order): W1[8], W2[64], Wlast[64], src[E], dst[E], graph_ids[N]
// Output: G*C float32
// ---------------------------------------------------------------------------
extern "C" void kernel_launch(void* const* d_in, const int* in_sizes, int n_in,
                              void* d_out, int out_size) {
    const float* W1    = (const float*)d_in[0];
    const float* W2    = (const float*)d_in[1];
    const float* Wlast = (const float*)d_in[2];
    const int*   src   = (const int*)d_in[3];
    const int*   dst   = (const int*)d_in[4];
    const int*   gid   = (const int*)d_in[5];

    int E = in_sizes[3];
    int N = in_sizes[5];
    int G = out_size / 8;
    float* out = (float*)d_out;

    void *pdeg, *pa1;
    cudaGetSymbolAddress(&pdeg, g_deg);
    cudaGetSymbolAddress(&pa1,  g_agg1);
    cudaMemsetAsync(pdeg, 0, (size_t)N * sizeof(unsigned));
    cudaMemsetAsync(pa1,  0, (size_t)N * sizeof(float));

    const int TB = 256;
    int nE8 = (E + 7) / 8;
    int gE8 = (nE8 + TB - 1) / TB;
    int gN  = (N + TB - 1) / TB;

    k_deg      <<<gE8, TB>>>(src, dst, E);
    k_scatter1 <<<gE8, TB>>>(src, dst, E);
    k_t        <<<gN,  TB>>>(N);
    k_scatter2 <<<gE8, TB>>>(src, dst, E);
    k_pool     <<<gN,  TB>>>(gid, N);
    k_final    <<<(G * 8 + TB - 1) / TB, TB>>>(W1, W2, Wlast, out, G);
}